// round 2
// baseline (speedup 1.0000x reference)
#include <cuda_runtime.h>
#include <math.h>

#define EMBED_DIM 512
#define NUM_HEADS 8
#define HEAD_DIM 64
#define T_LEN 128
#define BATCH 8
#define BH 64
#define SCALING 0.125f
#define LAMBDA 1.0f
#define TA 16   // a-rows per block in main kernel

// Scratch (allocation-free rule: __device__ globals)
__device__ float g_q[BH * T_LEN * HEAD_DIM];     // [i][t][hd], scaled
__device__ float g_k[BH * T_LEN * HEAD_DIM];
__device__ float g_v[BH * T_LEN * HEAD_DIM];
__device__ float g_attn2[T_LEN * BATCH * EMBED_DIM];  // [t][b][h*64+d]

// ---------------------------------------------------------------------------
// Kernel A: fused in-projection  out = X_s @ W_s^T + b_s  -> q/k/v [i][t][hd]
// Tiles: 128 rows (t*8+b) x 64 cols (j), K=512 in chunks of 16.
// ---------------------------------------------------------------------------
__global__ __launch_bounds__(256) void proj_in_kernel(
    const float* __restrict__ q_in, const float* __restrict__ k_in,
    const float* __restrict__ v_in, const float* __restrict__ W,
    const float* __restrict__ bias)
{
    const int jbase = blockIdx.x * 64;     // 0..1535
    const int rbase = blockIdx.y * 128;    // 0..1023
    const int section = jbase / 512;       // 0=q,1=k,2=v
    const float* __restrict__ X = (section == 0) ? q_in : (section == 1) ? k_in : v_in;

    __shared__ float Xs[16][128];
    __shared__ float Ws[16][64];

    const int tid = threadIdx.x;
    const int tx = tid & 15;        // 16 col-groups of 4
    const int ty = tid >> 4;        // 16 row-groups of 8

    float acc[8][4];
#pragma unroll
    for (int i = 0; i < 8; i++)
#pragma unroll
        for (int j = 0; j < 4; j++) acc[i][j] = 0.f;

    for (int k0 = 0; k0 < 512; k0 += 16) {
        // load X tile [128][16] transposed into Xs[kk][r]
#pragma unroll
        for (int rep = 0; rep < 2; rep++) {
            int lin = rep * 256 + tid;
            int r = lin >> 2;
            int kk = (lin & 3) * 4;
            float4 xv = *(const float4*)&X[(size_t)(rbase + r) * 512 + k0 + kk];
            Xs[kk + 0][r] = xv.x; Xs[kk + 1][r] = xv.y;
            Xs[kk + 2][r] = xv.z; Xs[kk + 3][r] = xv.w;
        }
        // load W tile [64][16] transposed into Ws[kk][j]
        {
            int j = tid >> 2;
            int kk = (tid & 3) * 4;
            float4 wv = *(const float4*)&W[(size_t)(jbase + j) * 512 + k0 + kk];
            Ws[kk + 0][j] = wv.x; Ws[kk + 1][j] = wv.y;
            Ws[kk + 2][j] = wv.z; Ws[kk + 3][j] = wv.w;
        }
        __syncthreads();
#pragma unroll
        for (int kk = 0; kk < 16; kk++) {
            float a0[8], b0[4];
            *(float4*)&a0[0] = *(float4*)&Xs[kk][ty * 8];
            *(float4*)&a0[4] = *(float4*)&Xs[kk][ty * 8 + 4];
            *(float4*)&b0[0] = *(float4*)&Ws[kk][tx * 4];
#pragma unroll
            for (int i = 0; i < 8; i++)
#pragma unroll
                for (int j = 0; j < 4; j++) acc[i][j] += a0[i] * b0[j];
        }
        __syncthreads();
    }

    float* dst = (section == 0) ? g_q : (section == 1) ? g_k : g_v;
#pragma unroll
    for (int i = 0; i < 8; i++) {
        int r = rbase + ty * 8 + i;
        int t = r >> 3;
        int bb = r & 7;
#pragma unroll
        for (int j = 0; j < 4; j++) {
            int jg = jbase + tx * 4 + j;
            float val = acc[i][j] + bias[jg];
            int jj = jg & 511;
            int h = jj >> 6;
            int dp = jj & 63;
            if (section == 0) val *= SCALING;
            dst[(((size_t)(bb * 8 + h)) * 128 + t) * 64 + dp] = val;
        }
    }
}

// ---------------------------------------------------------------------------
// Kernel B: main fused trilinear + bias + mean/max + softmax + attn bmm.
// Block = (head, a_tile, batch). For each a in tile:
//   X_a[b,c] = sum_t q[a,t]*k[b,t]*v[c,t]  (128x128x64 GEMM, registers)
//   s = X + bias;  fused[a,b] = mean_c(s) + max_c(s)
// Then softmax over b, attn[a,:] = sum_b w[a,b] q[b,:], write [t][b][h*64+d].
// ---------------------------------------------------------------------------
__global__ __launch_bounds__(256, 2) void tri_main_kernel(
    const float* __restrict__ cbias)
{
    const int head  = blockIdx.x;   // 0..7
    const int atile = blockIdx.y;   // 0..7
    const int batch = blockIdx.z;   // 0..7
    const int i = batch * 8 + head;

    const float* __restrict__ qi = g_q + (size_t)i * 8192;
    const float* __restrict__ ki = g_k + (size_t)i * 8192;
    const float* __restrict__ vi = g_v + (size_t)i * 8192;

    extern __shared__ float smem[];
    float* kT    = smem;             // [64][128] kT[t*128+b]
    float* vT    = smem + 8192;      // [64][128]
    float* qs    = smem + 16384;     // [16][64]
    float* fused = smem + 17408;     // [16][128]

    const int tid = threadIdx.x;
    const int tx = tid & 15;   // c groups
    const int ty = tid >> 4;   // b groups
    const int b0 = ty * 8;
    const int c0 = tx * 8;

    // transpose-load k, v into smem [t][pos]
    for (int idx = tid; idx < 8192; idx += 256) {
        int b = idx >> 6;
        int t = idx & 63;
        float kvk = ki[idx];
        float kvv = vi[idx];
        kT[t * 128 + b] = kvk;
        vT[t * 128 + b] = kvv;
    }
    for (int idx = tid; idx < TA * 64; idx += 256)
        qs[idx] = qi[atile * (TA * 64) + idx];
    __syncthreads();

    const float* __restrict__ bias_base =
        cbias + (size_t)batch * 128 * 128 * 128;

#pragma unroll 1
    for (int a = 0; a < TA; a++) {
        float acc[8][8];
#pragma unroll
        for (int x = 0; x < 8; x++)
#pragma unroll
            for (int y = 0; y < 8; y++) acc[x][y] = 0.f;

        const float* __restrict__ qrow = qs + a * 64;
#pragma unroll 4
        for (int t = 0; t < 64; t++) {
            float qa = qrow[t];
            float kf[8], vf[8];
            *(float4*)&kf[0] = *(const float4*)&kT[t * 128 + b0];
            *(float4*)&kf[4] = *(const float4*)&kT[t * 128 + b0 + 4];
            *(float4*)&vf[0] = *(const float4*)&vT[t * 128 + c0];
            *(float4*)&vf[4] = *(const float4*)&vT[t * 128 + c0 + 4];
            float pk[8];
#pragma unroll
            for (int x = 0; x < 8; x++) pk[x] = qa * kf[x];
#pragma unroll
            for (int x = 0; x < 8; x++)
#pragma unroll
                for (int y = 0; y < 8; y++) acc[x][y] += pk[x] * vf[y];
        }

        // bias add + per-row (b) sum/max over this thread's 8 c values
        const int ag = atile * TA + a;
        const float* __restrict__ bp =
            bias_base + (size_t)ag * 128 * 128;
        float rsum[8], rmax[8];
#pragma unroll
        for (int x = 0; x < 8; x++) {
            const float* row = bp + (size_t)(b0 + x) * 128 + c0;
            float4 bA = *(const float4*)&row[0];
            float4 bB = *(const float4*)&row[4];
            float s0 = acc[x][0] + LAMBDA * bA.x;
            float s1 = acc[x][1] + LAMBDA * bA.y;
            float s2 = acc[x][2] + LAMBDA * bA.z;
            float s3 = acc[x][3] + LAMBDA * bA.w;
            float s4 = acc[x][4] + LAMBDA * bB.x;
            float s5 = acc[x][5] + LAMBDA * bB.y;
            float s6 = acc[x][6] + LAMBDA * bB.z;
            float s7 = acc[x][7] + LAMBDA * bB.w;
            rsum[x] = ((s0 + s1) + (s2 + s3)) + ((s4 + s5) + (s6 + s7));
            float m01 = fmaxf(s0, s1), m23 = fmaxf(s2, s3);
            float m45 = fmaxf(s4, s5), m67 = fmaxf(s6, s7);
            rmax[x] = fmaxf(fmaxf(m01, m23), fmaxf(m45, m67));
        }
        // reduce across the 16 tx lanes (stays inside half-warp: offsets < 16)
#pragma unroll
        for (int off = 8; off >= 1; off >>= 1) {
#pragma unroll
            for (int x = 0; x < 8; x++) {
                rsum[x] += __shfl_xor_sync(0xffffffffu, rsum[x], off);
                rmax[x] = fmaxf(rmax[x], __shfl_xor_sync(0xffffffffu, rmax[x], off));
            }
        }
        if (tx == 0) {
#pragma unroll
            for (int x = 0; x < 8; x++)
                fused[a * 128 + b0 + x] = rsum[x] * (1.0f / 128.0f) + rmax[x];
        }
    }
    __syncthreads();

    // softmax over b for each row a (warp per row, 2 rows per warp)
    {
        int w = tid >> 5;
        int lane = tid & 31;
        for (int a = w; a < TA; a += 8) {
            float4 fv = *(float4*)&fused[a * 128 + lane * 4];
            float m = fmaxf(fmaxf(fv.x, fv.y), fmaxf(fv.z, fv.w));
#pragma unroll
            for (int off = 16; off >= 1; off >>= 1)
                m = fmaxf(m, __shfl_xor_sync(0xffffffffu, m, off));
            float e0 = __expf(fv.x - m), e1 = __expf(fv.y - m);
            float e2 = __expf(fv.z - m), e3 = __expf(fv.w - m);
            float s = (e0 + e1) + (e2 + e3);
#pragma unroll
            for (int off = 16; off >= 1; off >>= 1)
                s += __shfl_xor_sync(0xffffffffu, s, off);
            float inv = 1.0f / s;
            float4 ov = make_float4(e0 * inv, e1 * inv, e2 * inv, e3 * inv);
            *(float4*)&fused[a * 128 + lane * 4] = ov;
        }
    }
    __syncthreads();

    // attn[a, d0..d0+3] = sum_b w[a,b] * q[b, d0..]
    {
        int a = tid >> 4;            // 16 rows
        int d0 = (tid & 15) * 4;     // 64 cols
        float o0 = 0.f, o1 = 0.f, o2 = 0.f, o3 = 0.f;
        const float* wrow = fused + a * 128;
#pragma unroll 4
        for (int b = 0; b < 128; b++) {
            float wb = wrow[b];
            float4 qv = *(const float4*)&qi[b * 64 + d0];
            o0 += wb * qv.x; o1 += wb * qv.y;
            o2 += wb * qv.z; o3 += wb * qv.w;
        }
        int t = atile * TA + a;
        float* dst = g_attn2 + ((size_t)t * 8 + batch) * 512 + head * 64 + d0;
        *(float4*)dst = make_float4(o0, o1, o2, o3);
    }
}

// ---------------------------------------------------------------------------
// Kernel C: output projection  out[r][dd] = attn2[r][:] . out_w[dd][:] + out_b
// ---------------------------------------------------------------------------
__global__ __launch_bounds__(256) void proj_out_kernel(
    const float* __restrict__ W, const float* __restrict__ bias,
    float* __restrict__ out)
{
    const int jbase = blockIdx.x * 64;     // 0..511
    const int rbase = blockIdx.y * 128;    // 0..1023
    const float* __restrict__ X = g_attn2;

    __shared__ float Xs[16][128];
    __shared__ float Ws[16][64];

    const int tid = threadIdx.x;
    const int tx = tid & 15;
    const int ty = tid >> 4;

    float acc[8][4];
#pragma unroll
    for (int i = 0; i < 8; i++)
#pragma unroll
        for (int j = 0; j < 4; j++) acc[i][j] = 0.f;

    for (int k0 = 0; k0 < 512; k0 += 16) {
#pragma unroll
        for (int rep = 0; rep < 2; rep++) {
            int lin = rep * 256 + tid;
            int r = lin >> 2;
            int kk = (lin & 3) * 4;
            float4 xv = *(const float4*)&X[(size_t)(rbase + r) * 512 + k0 + kk];
            Xs[kk + 0][r] = xv.x; Xs[kk + 1][r] = xv.y;
            Xs[kk + 2][r] = xv.z; Xs[kk + 3][r] = xv.w;
        }
        {
            int j = tid >> 2;
            int kk = (tid & 3) * 4;
            float4 wv = *(const float4*)&W[(size_t)(jbase + j) * 512 + k0 + kk];
            Ws[kk + 0][j] = wv.x; Ws[kk + 1][j] = wv.y;
            Ws[kk + 2][j] = wv.z; Ws[kk + 3][j] = wv.w;
        }
        __syncthreads();
#pragma unroll
        for (int kk = 0; kk < 16; kk++) {
            float a0[8], b0[4];
            *(float4*)&a0[0] = *(float4*)&Xs[kk][ty * 8];
            *(float4*)&a0[4] = *(float4*)&Xs[kk][ty * 8 + 4];
            *(float4*)&b0[0] = *(float4*)&Ws[kk][tx * 4];
#pragma unroll
            for (int i = 0; i < 8; i++)
#pragma unroll
                for (int j = 0; j < 4; j++) acc[i][j] += a0[i] * b0[j];
        }
        __syncthreads();
    }

#pragma unroll
    for (int i = 0; i < 8; i++) {
        int r = rbase + ty * 8 + i;
#pragma unroll
        for (int j = 0; j < 4; j++) {
            int jg = jbase + tx * 4 + j;
            out[(size_t)r * 512 + jg] = acc[i][j] + bias[jg];
        }
    }
}

// ---------------------------------------------------------------------------
extern "C" void kernel_launch(void* const* d_in, const int* in_sizes, int n_in,
                              void* d_out, int out_size)
{
    const float* query = (const float*)d_in[0];   // [128,8,512]
    const float* key   = (const float*)d_in[1];
    const float* value = (const float*)d_in[2];
    const float* cbias = (const float*)d_in[3];   // [8,128,128,128]
    const float* ipw   = (const float*)d_in[4];   // [1536,512]
    const float* ipb   = (const float*)d_in[5];   // [1536]
    const float* outw  = (const float*)d_in[6];   // [512,512]
    const float* outb  = (const float*)d_in[7];   // [512]
    float* out = (float*)d_out;                   // [128,8,512]

    // in-projection: 24 col-tiles x 8 row-tiles
    proj_in_kernel<<<dim3(24, 8), 256>>>(query, key, value, ipw, ipb);

    // main fused kernel: needs >48KB dynamic smem
    static const size_t SMEM_B = (8192 + 8192 + TA * 64 + TA * 128) * sizeof(float);
    cudaFuncSetAttribute(tri_main_kernel,
                         cudaFuncAttributeMaxDynamicSharedMemorySize,
                         (int)SMEM_B);
    tri_main_kernel<<<dim3(8, 8, 8), 256, SMEM_B>>>(cbias);

    // out-projection
    proj_out_kernel<<<dim3(8, 8), 256>>>(outw, outb, out);
}

// round 4
// speedup vs baseline: 1.8977x; 1.8977x over previous
#include <cuda_runtime.h>
#include <cuda_bf16.h>
#include <math.h>
#include <stdint.h>

#define EMBED_DIM 512
#define NUM_HEADS 8
#define HEAD_DIM 64
#define T_LEN 128
#define BATCH 8
#define BH 64
#define SCALING 0.125f
#define LAMBDA 1.0f

// Scratch (allocation-free rule: __device__ globals)
__device__ float g_q[BH * T_LEN * HEAD_DIM];     // [i][t][hd], scaled
__device__ float g_k[BH * T_LEN * HEAD_DIM];
__device__ float g_v[BH * T_LEN * HEAD_DIM];
__device__ float g_attn2[T_LEN * BATCH * EMBED_DIM];  // [t][b][h*64+d]

// ---------------------------------------------------------------------------
// helpers (base ISA only: ldmatrix + mma.sync — no tcgen05 on this toolchain)
// ---------------------------------------------------------------------------
__device__ __forceinline__ uint32_t smem_u32(const void* p) {
    uint32_t a;
    asm("{ .reg .u64 t; cvta.to.shared.u64 t, %1; cvt.u32.u64 %0, t; }"
        : "=r"(a) : "l"(p));
    return a;
}

__device__ __forceinline__ void ldmatrix_x4(uint32_t& r0, uint32_t& r1,
                                            uint32_t& r2, uint32_t& r3,
                                            uint32_t addr) {
    asm volatile("ldmatrix.sync.aligned.m8n8.x4.shared.b16 {%0,%1,%2,%3}, [%4];"
                 : "=r"(r0), "=r"(r1), "=r"(r2), "=r"(r3) : "r"(addr));
}

__device__ __forceinline__ void mma_bf16(float* c, uint32_t a0, uint32_t a1,
                                         uint32_t a2, uint32_t a3,
                                         uint32_t b0, uint32_t b1) {
    asm volatile(
        "mma.sync.aligned.m16n8k16.row.col.f32.bf16.bf16.f32 "
        "{%0,%1,%2,%3}, {%4,%5,%6,%7}, {%8,%9}, {%0,%1,%2,%3};"
        : "+f"(c[0]), "+f"(c[1]), "+f"(c[2]), "+f"(c[3])
        : "r"(a0), "r"(a1), "r"(a2), "r"(a3), "r"(b0), "r"(b1));
}

// pack low halves of two fp32 into bf16x2 word (rn): low16 = x0, high16 = x1
__device__ __forceinline__ uint32_t cvt_bf16x2(float x1, float x0) {
    uint32_t w;
    asm("cvt.rn.bf16x2.f32 %0, %1, %2;" : "=r"(w) : "f"(x1), "f"(x0));
    return w;
}

// SMEM layout (bytes). Rows padded to 144B (64 bf16 + 8 pad) => conflict-free
// ldmatrix (36 words/row: 8-row groups land on distinct bank quads).
#define ROWB 144
#define SM_VHI   0
#define SM_VLO   18432
#define SM_A     36864            /* per warp: [Ah 2304][Al 2304] */
#define SM_QS    73728            /* [128][64] f32 */
#define SM_FUSED 106496           /* [64][128] f32 */
#define SM_TOTAL 139264

// ---------------------------------------------------------------------------
// Kernel A: fused in-projection  out = X_s @ W_s^T + b_s  -> q/k/v [i][t][hd]
// 64-row x 64-col tiles, grid (24, 16)
// ---------------------------------------------------------------------------
__global__ __launch_bounds__(256) void proj_in_kernel(
    const float* __restrict__ q_in, const float* __restrict__ k_in,
    const float* __restrict__ v_in, const float* __restrict__ W,
    const float* __restrict__ bias)
{
    const int jbase = blockIdx.x * 64;     // 0..1535
    const int rbase = blockIdx.y * 64;     // 0..1023
    const int section = jbase / 512;       // 0=q,1=k,2=v
    const float* __restrict__ X = (section == 0) ? q_in : (section == 1) ? k_in : v_in;

    __shared__ float Xs[16][64];
    __shared__ float Ws[16][64];

    const int tid = threadIdx.x;
    const int tx = tid & 15;
    const int ty = tid >> 4;

    float acc[4][4];
#pragma unroll
    for (int i = 0; i < 4; i++)
#pragma unroll
        for (int j = 0; j < 4; j++) acc[i][j] = 0.f;

    for (int k0 = 0; k0 < 512; k0 += 16) {
        {
            int r = tid >> 2;
            int kk = (tid & 3) * 4;
            float4 xv = *(const float4*)&X[(size_t)(rbase + r) * 512 + k0 + kk];
            Xs[kk + 0][r] = xv.x; Xs[kk + 1][r] = xv.y;
            Xs[kk + 2][r] = xv.z; Xs[kk + 3][r] = xv.w;
            float4 wv = *(const float4*)&W[(size_t)(jbase + r) * 512 + k0 + kk];
            Ws[kk + 0][r] = wv.x; Ws[kk + 1][r] = wv.y;
            Ws[kk + 2][r] = wv.z; Ws[kk + 3][r] = wv.w;
        }
        __syncthreads();
#pragma unroll
        for (int kk = 0; kk < 16; kk++) {
            float a0[4], b0[4];
            *(float4*)&a0[0] = *(float4*)&Xs[kk][ty * 4];
            *(float4*)&b0[0] = *(float4*)&Ws[kk][tx * 4];
#pragma unroll
            for (int i = 0; i < 4; i++)
#pragma unroll
                for (int j = 0; j < 4; j++) acc[i][j] += a0[i] * b0[j];
        }
        __syncthreads();
    }

    float* dst = (section == 0) ? g_q : (section == 1) ? g_k : g_v;
#pragma unroll
    for (int i = 0; i < 4; i++) {
        int r = rbase + ty * 4 + i;
        int t = r >> 3;
        int bb = r & 7;
#pragma unroll
        for (int j = 0; j < 4; j++) {
            int jg = jbase + tx * 4 + j;
            float val = acc[i][j] + bias[jg];
            int jj = jg & 511;
            int h = jj >> 6;
            int dp = jj & 63;
            if (section == 0) val *= SCALING;
            dst[(((size_t)(bb * 8 + h)) * 128 + t) * 64 + dp] = val;
        }
    }
}

// ---------------------------------------------------------------------------
// Kernel B v3: mma.sync trilinear + bias + mean/max + softmax + attn bmm.
// Block = (head, ahalf, batch) -> 64 'a' rows of pair i. 8 warps, warp w owns
// b-rows [w*16, w*16+16). Per a (warp-independent, no block sync):
//   A[b,t] = k[b,t]*q_a[t], truncation-split hi/lo bf16 -> warp-private smem
//   S = Ah*Vh + Ah*Vl + Al*Vh  via mma.sync m16n8k16 (regs accumulate)
//   epilogue on fragments: +bias, running sum & max over c
// ---------------------------------------------------------------------------
__global__ __launch_bounds__(256, 1) void tri_main_v3(const float* __restrict__ cbias)
{
    const int head  = blockIdx.x;   // 0..7
    const int ahalf = blockIdx.y;   // 0..1
    const int batch = blockIdx.z;   // 0..7
    const int i = batch * 8 + head;
    const int a0 = ahalf * 64;

    extern __shared__ char smem[];
    const uint32_t sbase = smem_u32(smem);
    float* qs    = (float*)(smem + SM_QS);
    float* fused = (float*)(smem + SM_FUSED);

    const int tid  = threadIdx.x;
    const int wid  = tid >> 5;
    const int lane = tid & 31;

    const float* __restrict__ qi = g_q + (size_t)i * 8192;
    const float* __restrict__ ki = g_k + (size_t)i * 8192;
    const float* __restrict__ vi = g_v + (size_t)i * 8192;

    // qs <- full q (scaled), needed by prep and final bmm
    for (int idx = tid; idx < 8192; idx += 256) qs[idx] = qi[idx];

    // V hi/lo split into padded rows. thread: row=tid/2, t-half=(tid&1)*32
    {
        const int row = tid >> 1;
        const int th = (tid & 1) * 32;
        char* vh = smem + SM_VHI + row * ROWB;
        char* vl = smem + SM_VLO + row * ROWB;
        const float* src = vi + row * 64 + th;
#pragma unroll
        for (int j = 0; j < 32; j += 4) {
            float x0 = src[j], x1 = src[j + 1], x2 = src[j + 2], x3 = src[j + 3];
            uint32_t u0 = __float_as_uint(x0), u1 = __float_as_uint(x1);
            uint32_t u2 = __float_as_uint(x2), u3 = __float_as_uint(x3);
            uint32_t hw0 = __byte_perm(u0, u1, 0x7632);
            uint32_t hw1 = __byte_perm(u2, u3, 0x7632);
            float l0 = x0 - __uint_as_float(u0 & 0xFFFF0000u);
            float l1 = x1 - __uint_as_float(u1 & 0xFFFF0000u);
            float l2 = x2 - __uint_as_float(u2 & 0xFFFF0000u);
            float l3 = x3 - __uint_as_float(u3 & 0xFFFF0000u);
            uint32_t lw0 = cvt_bf16x2(l1, l0);
            uint32_t lw1 = cvt_bf16x2(l3, l2);
            *(uint2*)(vh + (th + j) * 2) = make_uint2(hw0, hw1);
            *(uint2*)(vl + (th + j) * 2) = make_uint2(lw0, lw1);
        }
    }

    // K rows for this warp in registers: lane l -> local row l/2, t-half
    const int rloc = lane >> 1;
    const int th = (lane & 1) * 32;
    float kreg[32];
#pragma unroll
    for (int j = 0; j < 32; j++) kreg[j] = ki[(wid * 16 + rloc) * 64 + th + j];

    __syncthreads();

    // Precomputed ldmatrix addresses
    const uint32_t abase = sbase + SM_A + wid * 4608;  // [Ah 2304][Al 2304]
    const uint32_t a_ld = abase + (lane & 15) * ROWB + ((lane >= 16) ? 16 : 0);
    uint32_t v_ld;  // per-lane base for combined (Vh b0,b1 | Vl b0,b1) x4 load
    {
        int p = lane >> 3, r8 = lane & 7;
        uint32_t off = (p & 1) ? 16u : 0u;
        uint32_t buf = (p >= 2) ? (uint32_t)SM_VLO : (uint32_t)SM_VHI;
        v_ld = sbase + buf + r8 * ROWB + off;
    }

    const int g = lane >> 2;       // fragment row group
    const int tig = lane & 3;      // fragment col pair
    const int browA = wid * 16 + g;
    const float* __restrict__ bias_b = cbias + ((size_t)batch << 21);

    char* ah = smem + SM_A + wid * 4608;
    char* al = ah + 2304;

#pragma unroll 1
    for (int a = 0; a < 64; a++) {
        __syncwarp();
        // ---- prep A hi/lo for this a (warp-private rows) ----
        {
            const float* qrow = qs + (a0 + a) * 64 + th;
            char* dh = ah + rloc * ROWB;
            char* dl = al + rloc * ROWB;
#pragma unroll
            for (int j = 0; j < 32; j += 4) {
                float x0 = kreg[j] * qrow[j];
                float x1 = kreg[j + 1] * qrow[j + 1];
                float x2 = kreg[j + 2] * qrow[j + 2];
                float x3 = kreg[j + 3] * qrow[j + 3];
                uint32_t u0 = __float_as_uint(x0), u1 = __float_as_uint(x1);
                uint32_t u2 = __float_as_uint(x2), u3 = __float_as_uint(x3);
                uint32_t hw0 = __byte_perm(u0, u1, 0x7632);
                uint32_t hw1 = __byte_perm(u2, u3, 0x7632);
                float l0 = x0 - __uint_as_float(u0 & 0xFFFF0000u);
                float l1 = x1 - __uint_as_float(u1 & 0xFFFF0000u);
                float l2 = x2 - __uint_as_float(u2 & 0xFFFF0000u);
                float l3 = x3 - __uint_as_float(u3 & 0xFFFF0000u);
                uint32_t lw0 = cvt_bf16x2(l1, l0);
                uint32_t lw1 = cvt_bf16x2(l3, l2);
                *(uint2*)(dh + (th + j) * 2) = make_uint2(hw0, hw1);
                *(uint2*)(dl + (th + j) * 2) = make_uint2(lw0, lw1);
            }
        }
        __syncwarp();

        // ---- load A fragments (4 k-steps x hi/lo) ----
        uint32_t fah[4][4], fal[4][4];
#pragma unroll
        for (int ks = 0; ks < 4; ks++) {
            ldmatrix_x4(fah[ks][0], fah[ks][1], fah[ks][2], fah[ks][3],
                        a_ld + ks * 32);
            ldmatrix_x4(fal[ks][0], fal[ks][1], fal[ks][2], fal[ks][3],
                        a_ld + 2304 + ks * 32);
        }

        const int ag = a0 + a;
        const float* __restrict__ bp =
            bias_b + ((size_t)ag << 14) + (size_t)browA * 128;
        float psum0 = 0.f, psum1 = 0.f, pmax0 = -1e30f, pmax1 = -1e30f;

#pragma unroll 4
        for (int nc = 0; nc < 16; nc++) {
            float c[4] = {0.f, 0.f, 0.f, 0.f};
#pragma unroll
            for (int ks = 0; ks < 4; ks++) {
                uint32_t bh0, bh1, bl0, bl1;
                ldmatrix_x4(bh0, bh1, bl0, bl1, v_ld + nc * (8 * ROWB) + ks * 32);
                mma_bf16(c, fah[ks][0], fah[ks][1], fah[ks][2], fah[ks][3], bh0, bh1);
                mma_bf16(c, fah[ks][0], fah[ks][1], fah[ks][2], fah[ks][3], bl0, bl1);
                mma_bf16(c, fal[ks][0], fal[ks][1], fal[ks][2], fal[ks][3], bh0, bh1);
            }
            const int col = nc * 8 + 2 * tig;
            float2 b0 = *(const float2*)&bp[col];
            float2 b1 = *(const float2*)&bp[8 * 128 + col];
            float s0 = c[0] + b0.x, s1 = c[1] + b0.y;
            float s2 = c[2] + b1.x, s3 = c[3] + b1.y;
            psum0 += s0 + s1;
            psum1 += s2 + s3;
            pmax0 = fmaxf(pmax0, fmaxf(s0, s1));
            pmax1 = fmaxf(pmax1, fmaxf(s2, s3));
        }
        // quad reduce (cols spread over 4 tig lanes)
#pragma unroll
        for (int off = 1; off <= 2; off <<= 1) {
            psum0 += __shfl_xor_sync(0xffffffffu, psum0, off);
            psum1 += __shfl_xor_sync(0xffffffffu, psum1, off);
            pmax0 = fmaxf(pmax0, __shfl_xor_sync(0xffffffffu, pmax0, off));
            pmax1 = fmaxf(pmax1, __shfl_xor_sync(0xffffffffu, pmax1, off));
        }
        if (tig == 0) {
            fused[a * 128 + browA] = psum0 * (1.0f / 128.0f) + pmax0;
            fused[a * 128 + browA + 8] = psum1 * (1.0f / 128.0f) + pmax1;
        }
    }
    __syncthreads();

    // Softmax over b for each of the 64 rows (one warp per row, round-robin)
    for (int a = wid; a < 64; a += 8) {
        float4 fv = *(float4*)&fused[a * 128 + lane * 4];
        float m = fmaxf(fmaxf(fv.x, fv.y), fmaxf(fv.z, fv.w));
#pragma unroll
        for (int off = 16; off >= 1; off >>= 1)
            m = fmaxf(m, __shfl_xor_sync(0xffffffffu, m, off));
        float e0 = __expf(fv.x - m), e1 = __expf(fv.y - m);
        float e2 = __expf(fv.z - m), e3 = __expf(fv.w - m);
        float s = (e0 + e1) + (e2 + e3);
#pragma unroll
        for (int off = 16; off >= 1; off >>= 1)
            s += __shfl_xor_sync(0xffffffffu, s, off);
        float inv = 1.0f / s;
        *(float4*)&fused[a * 128 + lane * 4] =
            make_float4(e0 * inv, e1 * inv, e2 * inv, e3 * inv);
    }
    __syncthreads();

    // attn[a, :] = sum_b w[a,b] q[b,:]; thread: a=tid/4 (64 rows), 16 cols
    {
        int a = tid >> 2;
        int dg = (tid & 3) * 16;
        float o[16];
#pragma unroll
        for (int j = 0; j < 16; j++) o[j] = 0.f;
        const float* wrow = fused + a * 128;
#pragma unroll 2
        for (int b = 0; b < 128; b++) {
            float wb = wrow[b];
            const float* qr = qs + b * 64 + dg;
#pragma unroll
            for (int m = 0; m < 4; m++) {
                float4 qv = *(const float4*)&qr[m * 4];
                o[m * 4 + 0] += wb * qv.x; o[m * 4 + 1] += wb * qv.y;
                o[m * 4 + 2] += wb * qv.z; o[m * 4 + 3] += wb * qv.w;
            }
        }
        int t = a0 + a;
        float* dst = g_attn2 + ((size_t)t * 8 + batch) * 512 + head * 64 + dg;
#pragma unroll
        for (int m = 0; m < 4; m++)
            *(float4*)&dst[m * 4] =
                make_float4(o[m * 4], o[m * 4 + 1], o[m * 4 + 2], o[m * 4 + 3]);
    }
}

// ---------------------------------------------------------------------------
// Kernel C: output projection (64-row x 64-col tiles, grid (8, 16))
// ---------------------------------------------------------------------------
__global__ __launch_bounds__(256) void proj_out_kernel(
    const float* __restrict__ W, const float* __restrict__ bias,
    float* __restrict__ out)
{
    const int jbase = blockIdx.x * 64;
    const int rbase = blockIdx.y * 64;
    const float* __restrict__ X = g_attn2;

    __shared__ float Xs[16][64];
    __shared__ float Ws[16][64];

    const int tid = threadIdx.x;
    const int tx = tid & 15;
    const int ty = tid >> 4;

    float acc[4][4];
#pragma unroll
    for (int i = 0; i < 4; i++)
#pragma unroll
        for (int j = 0; j < 4; j++) acc[i][j] = 0.f;

    for (int k0 = 0; k0 < 512; k0 += 16) {
        {
            int r = tid >> 2;
            int kk = (tid & 3) * 4;
            float4 xv = *(const float4*)&X[(size_t)(rbase + r) * 512 + k0 + kk];
            Xs[kk + 0][r] = xv.x; Xs[kk + 1][r] = xv.y;
            Xs[kk + 2][r] = xv.z; Xs[kk + 3][r] = xv.w;
            float4 wv = *(const float4*)&W[(size_t)(jbase + r) * 512 + k0 + kk];
            Ws[kk + 0][r] = wv.x; Ws[kk + 1][r] = wv.y;
            Ws[kk + 2][r] = wv.z; Ws[kk + 3][r] = wv.w;
        }
        __syncthreads();
#pragma unroll
        for (int kk = 0; kk < 16; kk++) {
            float a0[4], b0[4];
            *(float4*)&a0[0] = *(float4*)&Xs[kk][ty * 4];
            *(float4*)&b0[0] = *(float4*)&Ws[kk][tx * 4];
#pragma unroll
            for (int i = 0; i < 4; i++)
#pragma unroll
                for (int j = 0; j < 4; j++) acc[i][j] += a0[i] * b0[j];
        }
        __syncthreads();
    }

#pragma unroll
    for (int i = 0; i < 4; i++) {
        int r = rbase + ty * 4 + i;
#pragma unroll
        for (int j = 0; j < 4; j++) {
            int jg = jbase + tx * 4 + j;
            out[(size_t)r * 512 + jg] = acc[i][j] + bias[jg];
        }
    }
}

// ---------------------------------------------------------------------------
extern "C" void kernel_launch(void* const* d_in, const int* in_sizes, int n_in,
                              void* d_out, int out_size)
{
    const float* query = (const float*)d_in[0];
    const float* key   = (const float*)d_in[1];
    const float* value = (const float*)d_in[2];
    const float* cbias = (const float*)d_in[3];
    const float* ipw   = (const float*)d_in[4];
    const float* ipb   = (const float*)d_in[5];
    const float* outw  = (const float*)d_in[6];
    const float* outb  = (const float*)d_in[7];
    float* out = (float*)d_out;

    proj_in_kernel<<<dim3(24, 16), 256>>>(query, key, value, ipw, ipb);

    cudaFuncSetAttribute(tri_main_v3,
                         cudaFuncAttributeMaxDynamicSharedMemorySize, SM_TOTAL);
    tri_main_v3<<<dim3(8, 2, 8), 256, SM_TOTAL>>>(cbias);

    proj_out_kernel<<<dim3(8, 16), 256>>>(outw, outb, out);
}

// round 5
// speedup vs baseline: 2.0567x; 1.0838x over previous
#include <cuda_runtime.h>
#include <cuda_bf16.h>
#include <math.h>
#include <stdint.h>

#define EMBED_DIM 512
#define NUM_HEADS 8
#define HEAD_DIM 64
#define T_LEN 128
#define BATCH 8
#define BH 64
#define SCALING 0.125f
#define LAMBDA 1.0f

// Scratch (allocation-free rule: __device__ globals)
__device__ float g_q[BH * T_LEN * HEAD_DIM];     // [i][t][hd], scaled
__device__ float g_k[BH * T_LEN * HEAD_DIM];
__device__ float g_v[BH * T_LEN * HEAD_DIM];
__device__ float g_attn2[T_LEN * BATCH * EMBED_DIM];  // [t][b][h*64+d]

// ---------------------------------------------------------------------------
// helpers (base ISA only: ldmatrix + mma.sync)
// ---------------------------------------------------------------------------
__device__ __forceinline__ uint32_t smem_u32(const void* p) {
    uint32_t a;
    asm("{ .reg .u64 t; cvta.to.shared.u64 t, %1; cvt.u32.u64 %0, t; }"
        : "=r"(a) : "l"(p));
    return a;
}

__device__ __forceinline__ void ldmatrix_x4(uint32_t& r0, uint32_t& r1,
                                            uint32_t& r2, uint32_t& r3,
                                            uint32_t addr) {
    asm volatile("ldmatrix.sync.aligned.m8n8.x4.shared.b16 {%0,%1,%2,%3}, [%4];"
                 : "=r"(r0), "=r"(r1), "=r"(r2), "=r"(r3) : "r"(addr));
}

__device__ __forceinline__ void mma_f16(float* c, uint32_t a0, uint32_t a1,
                                        uint32_t a2, uint32_t a3,
                                        uint32_t b0, uint32_t b1) {
    asm volatile(
        "mma.sync.aligned.m16n8k16.row.col.f32.f16.f16.f32 "
        "{%0,%1,%2,%3}, {%4,%5,%6,%7}, {%8,%9}, {%0,%1,%2,%3};"
        : "+f"(c[0]), "+f"(c[1]), "+f"(c[2]), "+f"(c[3])
        : "r"(a0), "r"(a1), "r"(a2), "r"(a3), "r"(b0), "r"(b1));
}

// pack two fp32 into f16x2 word: low16 = x0, high16 = x1
__device__ __forceinline__ uint32_t cvt_f16x2(float x1, float x0) {
    uint32_t w;
    asm("cvt.rn.f16x2.f32 %0, %1, %2;" : "=r"(w) : "f"(x1), "f"(x0));
    return w;
}

// SMEM layout (bytes). Rows padded to 144B (64 f16 + 8 pad) => conflict-free.
#define ROWB 144
#define SM_V     0                /* 128 * 144 = 18432 */
#define SM_A     18432            /* 8 warps * 2 bufs * 2304 = 36864 */
#define SM_QS    55296            /* [128][64] f32 = 32768 */
#define SM_FUSED 88064            /* [64][128] f32 = 32768 */
#define SM_TOTAL 120832

// ---------------------------------------------------------------------------
// Kernel A: fused in-projection  out = X_s @ W_s^T + b_s  -> q/k/v [i][t][hd]
// 32-row x 64-col tiles, grid (24, 32) = 768 blocks (occupancy fix)
// ---------------------------------------------------------------------------
__global__ __launch_bounds__(256) void proj_in_kernel(
    const float* __restrict__ q_in, const float* __restrict__ k_in,
    const float* __restrict__ v_in, const float* __restrict__ W,
    const float* __restrict__ bias)
{
    const int jbase = blockIdx.x * 64;     // 0..1535
    const int rbase = blockIdx.y * 32;     // 0..1023
    const int section = jbase / 512;       // 0=q,1=k,2=v
    const float* __restrict__ X = (section == 0) ? q_in : (section == 1) ? k_in : v_in;

    __shared__ float Xs[16][32];
    __shared__ float Ws[16][64];

    const int tid = threadIdx.x;
    const int tx = tid & 15;
    const int ty = tid >> 4;

    float acc[2][4];
#pragma unroll
    for (int i = 0; i < 2; i++)
#pragma unroll
        for (int j = 0; j < 4; j++) acc[i][j] = 0.f;

    for (int k0 = 0; k0 < 512; k0 += 16) {
        {
            int r = tid >> 2;
            int kk = (tid & 3) * 4;
            float4 wv = *(const float4*)&W[(size_t)(jbase + r) * 512 + k0 + kk];
            Ws[kk + 0][r] = wv.x; Ws[kk + 1][r] = wv.y;
            Ws[kk + 2][r] = wv.z; Ws[kk + 3][r] = wv.w;
            if (tid < 128) {
                float4 xv = *(const float4*)&X[(size_t)(rbase + r) * 512 + k0 + kk];
                Xs[kk + 0][r] = xv.x; Xs[kk + 1][r] = xv.y;
                Xs[kk + 2][r] = xv.z; Xs[kk + 3][r] = xv.w;
            }
        }
        __syncthreads();
#pragma unroll
        for (int kk = 0; kk < 16; kk++) {
            float a0[2], b0[4];
            a0[0] = Xs[kk][ty * 2];
            a0[1] = Xs[kk][ty * 2 + 1];
            *(float4*)&b0[0] = *(float4*)&Ws[kk][tx * 4];
#pragma unroll
            for (int i = 0; i < 2; i++)
#pragma unroll
                for (int j = 0; j < 4; j++) acc[i][j] += a0[i] * b0[j];
        }
        __syncthreads();
    }

    float* dst = (section == 0) ? g_q : (section == 1) ? g_k : g_v;
#pragma unroll
    for (int i = 0; i < 2; i++) {
        int r = rbase + ty * 2 + i;
        int t = r >> 3;
        int bb = r & 7;
#pragma unroll
        for (int j = 0; j < 4; j++) {
            int jg = jbase + tx * 4 + j;
            float val = acc[i][j] + bias[jg];
            int jj = jg & 511;
            int h = jj >> 6;
            int dp = jj & 63;
            if (section == 0) val *= SCALING;
            dst[(((size_t)(bb * 8 + h)) * 128 + t) * 64 + dp] = val;
        }
    }
}

// ---------------------------------------------------------------------------
// Kernel B v4: single-pass fp16 mma.sync trilinear + bias + mean/max
//              + softmax + attn bmm.
// Block = (head, ahalf, batch) -> 64 'a' rows of pair i. Warp w owns b-rows
// [w*16, w*16+16). Two 'a' rows per iteration share B (V) fragments.
// ---------------------------------------------------------------------------
__global__ __launch_bounds__(256, 1) void tri_main_v4(const float* __restrict__ cbias)
{
    const int head  = blockIdx.x;   // 0..7
    const int ahalf = blockIdx.y;   // 0..1
    const int batch = blockIdx.z;   // 0..7
    const int i = batch * 8 + head;
    const int a0 = ahalf * 64;

    extern __shared__ char smem[];
    const uint32_t sbase = smem_u32(smem);
    float* qs    = (float*)(smem + SM_QS);
    float* fused = (float*)(smem + SM_FUSED);

    const int tid  = threadIdx.x;
    const int wid  = tid >> 5;
    const int lane = tid & 31;

    const float* __restrict__ qi = g_q + (size_t)i * 8192;
    const float* __restrict__ ki = g_k + (size_t)i * 8192;
    const float* __restrict__ vi = g_v + (size_t)i * 8192;

    // qs <- full q (scaled), needed by prep and final bmm
    for (int idx = tid; idx < 8192; idx += 256) qs[idx] = qi[idx];

    // V -> fp16 padded rows. thread: row=tid/2, t-half=(tid&1)*32
    {
        const int row = tid >> 1;
        const int th = (tid & 1) * 32;
        char* vd = smem + SM_V + row * ROWB;
        const float* src = vi + row * 64 + th;
#pragma unroll
        for (int j = 0; j < 32; j += 4) {
            float x0 = src[j], x1 = src[j + 1], x2 = src[j + 2], x3 = src[j + 3];
            uint32_t w0 = cvt_f16x2(x1, x0);
            uint32_t w1 = cvt_f16x2(x3, x2);
            *(uint2*)(vd + (th + j) * 2) = make_uint2(w0, w1);
        }
    }

    // K rows for this warp in registers: lane l -> local row l/2, t-half
    const int rloc = lane >> 1;
    const int th = (lane & 1) * 32;
    float kreg[32];
#pragma unroll
    for (int j = 0; j < 32; j++) kreg[j] = ki[(wid * 16 + rloc) * 64 + th + j];

    __syncthreads();

    // ldmatrix addresses
    char* ah0 = smem + SM_A + wid * 4608;
    char* ah1 = ah0 + 2304;
    const uint32_t a_ld = sbase + SM_A + wid * 4608 +
                          (lane & 15) * ROWB + ((lane >= 16) ? 16 : 0);
    // V: x4 tiles = 4 consecutive k-octets of 8 n-rows
    const uint32_t v_ld = sbase + SM_V + (lane & 7) * ROWB + ((lane >> 3) * 16);

    const int g = lane >> 2;       // fragment row group
    const int tig = lane & 3;      // fragment col pair
    const int browA = wid * 16 + g;
    const float* __restrict__ bias_b = cbias + ((size_t)batch << 21);

#pragma unroll 1
    for (int ap = 0; ap < 32; ap++) {
        const int aA = 2 * ap, aB = 2 * ap + 1;
        __syncwarp();
        // ---- prep A for both a's (warp-private rows) ----
        {
            const float* q0 = qs + (a0 + aA) * 64 + th;
            const float* q1 = q0 + 64;
            char* d0 = ah0 + rloc * ROWB;
            char* d1 = ah1 + rloc * ROWB;
#pragma unroll
            for (int j = 0; j < 32; j += 4) {
                float x0 = kreg[j] * q0[j];
                float x1 = kreg[j + 1] * q0[j + 1];
                float x2 = kreg[j + 2] * q0[j + 2];
                float x3 = kreg[j + 3] * q0[j + 3];
                *(uint2*)(d0 + (th + j) * 2) =
                    make_uint2(cvt_f16x2(x1, x0), cvt_f16x2(x3, x2));
                float y0 = kreg[j] * q1[j];
                float y1 = kreg[j + 1] * q1[j + 1];
                float y2 = kreg[j + 2] * q1[j + 2];
                float y3 = kreg[j + 3] * q1[j + 3];
                *(uint2*)(d1 + (th + j) * 2) =
                    make_uint2(cvt_f16x2(y1, y0), cvt_f16x2(y3, y2));
            }
        }
        __syncwarp();

        // ---- load A fragments (4 k-steps, both a's) ----
        uint32_t fa0[4][4], fa1[4][4];
#pragma unroll
        for (int ks = 0; ks < 4; ks++) {
            ldmatrix_x4(fa0[ks][0], fa0[ks][1], fa0[ks][2], fa0[ks][3],
                        a_ld + ks * 32);
            ldmatrix_x4(fa1[ks][0], fa1[ks][1], fa1[ks][2], fa1[ks][3],
                        a_ld + 2304 + ks * 32);
        }

        const float* __restrict__ bpA =
            bias_b + ((size_t)(a0 + aA) << 14) + (size_t)browA * 128;
        const float* __restrict__ bpB = bpA + (1 << 14);
        float psA0 = 0.f, psA1 = 0.f, pmA0 = -1e30f, pmA1 = -1e30f;
        float psB0 = 0.f, psB1 = 0.f, pmB0 = -1e30f, pmB1 = -1e30f;

#pragma unroll 2
        for (int nc = 0; nc < 16; nc++) {
            uint32_t b[8];
            ldmatrix_x4(b[0], b[1], b[2], b[3], v_ld + nc * (8 * ROWB));
            ldmatrix_x4(b[4], b[5], b[6], b[7], v_ld + nc * (8 * ROWB) + 64);
            float c0[4] = {0.f, 0.f, 0.f, 0.f};
            float c1[4] = {0.f, 0.f, 0.f, 0.f};
#pragma unroll
            for (int ks = 0; ks < 4; ks++) {
                mma_f16(c0, fa0[ks][0], fa0[ks][1], fa0[ks][2], fa0[ks][3],
                        b[ks * 2], b[ks * 2 + 1]);
                mma_f16(c1, fa1[ks][0], fa1[ks][1], fa1[ks][2], fa1[ks][3],
                        b[ks * 2], b[ks * 2 + 1]);
            }
            const int col = nc * 8 + 2 * tig;
            float2 bA0 = *(const float2*)&bpA[col];
            float2 bA1 = *(const float2*)&bpA[8 * 128 + col];
            float2 bB0 = *(const float2*)&bpB[col];
            float2 bB1 = *(const float2*)&bpB[8 * 128 + col];
            {
                float s0 = c0[0] + bA0.x, s1 = c0[1] + bA0.y;
                float s2 = c0[2] + bA1.x, s3 = c0[3] + bA1.y;
                psA0 += s0 + s1; psA1 += s2 + s3;
                pmA0 = fmaxf(pmA0, fmaxf(s0, s1));
                pmA1 = fmaxf(pmA1, fmaxf(s2, s3));
            }
            {
                float s0 = c1[0] + bB0.x, s1 = c1[1] + bB0.y;
                float s2 = c1[2] + bB1.x, s3 = c1[3] + bB1.y;
                psB0 += s0 + s1; psB1 += s2 + s3;
                pmB0 = fmaxf(pmB0, fmaxf(s0, s1));
                pmB1 = fmaxf(pmB1, fmaxf(s2, s3));
            }
        }
        // quad reduce (cols spread over 4 tig lanes)
#pragma unroll
        for (int off = 1; off <= 2; off <<= 1) {
            psA0 += __shfl_xor_sync(0xffffffffu, psA0, off);
            psA1 += __shfl_xor_sync(0xffffffffu, psA1, off);
            psB0 += __shfl_xor_sync(0xffffffffu, psB0, off);
            psB1 += __shfl_xor_sync(0xffffffffu, psB1, off);
            pmA0 = fmaxf(pmA0, __shfl_xor_sync(0xffffffffu, pmA0, off));
            pmA1 = fmaxf(pmA1, __shfl_xor_sync(0xffffffffu, pmA1, off));
            pmB0 = fmaxf(pmB0, __shfl_xor_sync(0xffffffffu, pmB0, off));
            pmB1 = fmaxf(pmB1, __shfl_xor_sync(0xffffffffu, pmB1, off));
        }
        if (tig == 0) {
            fused[aA * 128 + browA]     = psA0 * (1.0f / 128.0f) + pmA0;
            fused[aA * 128 + browA + 8] = psA1 * (1.0f / 128.0f) + pmA1;
            fused[aB * 128 + browA]     = psB0 * (1.0f / 128.0f) + pmB0;
            fused[aB * 128 + browA + 8] = psB1 * (1.0f / 128.0f) + pmB1;
        }
    }
    __syncthreads();

    // Softmax over b for each of the 64 rows (one warp per row, round-robin)
    for (int a = wid; a < 64; a += 8) {
        float4 fv = *(float4*)&fused[a * 128 + lane * 4];
        float m = fmaxf(fmaxf(fv.x, fv.y), fmaxf(fv.z, fv.w));
#pragma unroll
        for (int off = 16; off >= 1; off >>= 1)
            m = fmaxf(m, __shfl_xor_sync(0xffffffffu, m, off));
        float e0 = __expf(fv.x - m), e1 = __expf(fv.y - m);
        float e2 = __expf(fv.z - m), e3 = __expf(fv.w - m);
        float s = (e0 + e1) + (e2 + e3);
#pragma unroll
        for (int off = 16; off >= 1; off >>= 1)
            s += __shfl_xor_sync(0xffffffffu, s, off);
        float inv = 1.0f / s;
        *(float4*)&fused[a * 128 + lane * 4] =
            make_float4(e0 * inv, e1 * inv, e2 * inv, e3 * inv);
    }
    __syncthreads();

    // attn[a, :] = sum_b w[a,b] q[b,:]; thread: a=tid/4 (64 rows), 16 cols
    {
        int a = tid >> 2;
        int dg = (tid & 3) * 16;
        float o[16];
#pragma unroll
        for (int j = 0; j < 16; j++) o[j] = 0.f;
        const float* wrow = fused + a * 128;
#pragma unroll 2
        for (int b = 0; b < 128; b++) {
            float wb = wrow[b];
            const float* qr = qs + b * 64 + dg;
#pragma unroll
            for (int m = 0; m < 4; m++) {
                float4 qv = *(const float4*)&qr[m * 4];
                o[m * 4 + 0] += wb * qv.x; o[m * 4 + 1] += wb * qv.y;
                o[m * 4 + 2] += wb * qv.z; o[m * 4 + 3] += wb * qv.w;
            }
        }
        int t = a0 + a;
        float* dst = g_attn2 + ((size_t)t * 8 + batch) * 512 + head * 64 + dg;
#pragma unroll
        for (int m = 0; m < 4; m++)
            *(float4*)&dst[m * 4] =
                make_float4(o[m * 4], o[m * 4 + 1], o[m * 4 + 2], o[m * 4 + 3]);
    }
}

// ---------------------------------------------------------------------------
// Kernel C: output projection (64-row x 64-col tiles, grid (8, 16))
// ---------------------------------------------------------------------------
__global__ __launch_bounds__(256) void proj_out_kernel(
    const float* __restrict__ W, const float* __restrict__ bias,
    float* __restrict__ out)
{
    const int jbase = blockIdx.x * 64;
    const int rbase = blockIdx.y * 64;
    const float* __restrict__ X = g_attn2;

    __shared__ float Xs[16][64];
    __shared__ float Ws[16][64];

    const int tid = threadIdx.x;
    const int tx = tid & 15;
    const int ty = tid >> 4;

    float acc[4][4];
#pragma unroll
    for (int i = 0; i < 4; i++)
#pragma unroll
        for (int j = 0; j < 4; j++) acc[i][j] = 0.f;

    for (int k0 = 0; k0 < 512; k0 += 16) {
        {
            int r = tid >> 2;
            int kk = (tid & 3) * 4;
            float4 xv = *(const float4*)&X[(size_t)(rbase + r) * 512 + k0 + kk];
            Xs[kk + 0][r] = xv.x; Xs[kk + 1][r] = xv.y;
            Xs[kk + 2][r] = xv.z; Xs[kk + 3][r] = xv.w;
            float4 wv = *(const float4*)&W[(size_t)(jbase + r) * 512 + k0 + kk];
            Ws[kk + 0][r] = wv.x; Ws[kk + 1][r] = wv.y;
            Ws[kk + 2][r] = wv.z; Ws[kk + 3][r] = wv.w;
        }
        __syncthreads();
#pragma unroll
        for (int kk = 0; kk < 16; kk++) {
            float a0[4], b0[4];
            *(float4*)&a0[0] = *(float4*)&Xs[kk][ty * 4];
            *(float4*)&b0[0] = *(float4*)&Ws[kk][tx * 4];
#pragma unroll
            for (int i = 0; i < 4; i++)
#pragma unroll
                for (int j = 0; j < 4; j++) acc[i][j] += a0[i] * b0[j];
        }
        __syncthreads();
    }

#pragma unroll
    for (int i = 0; i < 4; i++) {
        int r = rbase + ty * 4 + i;
#pragma unroll
        for (int j = 0; j < 4; j++) {
            int jg = jbase + tx * 4 + j;
            out[(size_t)r * 512 + jg] = acc[i][j] + bias[jg];
        }
    }
}

// ---------------------------------------------------------------------------
extern "C" void kernel_launch(void* const* d_in, const int* in_sizes, int n_in,
                              void* d_out, int out_size)
{
    const float* query = (const float*)d_in[0];
    const float* key   = (const float*)d_in[1];
    const float* value = (const float*)d_in[2];
    const float* cbias = (const float*)d_in[3];
    const float* ipw   = (const float*)d_in[4];
    const float* ipb   = (const float*)d_in[5];
    const float* outw  = (const float*)d_in[6];
    const float* outb  = (const float*)d_in[7];
    float* out = (float*)d_out;

    proj_in_kernel<<<dim3(24, 32), 256>>>(query, key, value, ipw, ipb);

    cudaFuncSetAttribute(tri_main_v4,
                         cudaFuncAttributeMaxDynamicSharedMemorySize, SM_TOTAL);
    tri_main_v4<<<dim3(8, 2, 8), 256, SM_TOTAL>>>(cbias);

    proj_out_kernel<<<dim3(8, 16), 256>>>(outw, outb, out);
}

// round 8
// speedup vs baseline: 2.7178x; 1.3214x over previous
#include <cuda_runtime.h>
#include <cuda_bf16.h>
#include <math.h>
#include <stdint.h>

#define EMBED_DIM 512
#define NUM_HEADS 8
#define HEAD_DIM 64
#define T_LEN 128
#define BATCH 8
#define BH 64
#define SCALING 0.125f
#define LAMBDA 1.0f

// Scratch (allocation-free rule: __device__ globals)
__device__ float g_q[BH * T_LEN * HEAD_DIM];     // [i][t][hd], scaled
__device__ float g_k[BH * T_LEN * HEAD_DIM];
__device__ float g_v[BH * T_LEN * HEAD_DIM];
__device__ float g_attn2[T_LEN * BATCH * EMBED_DIM];  // [t][b][h*64+d]

// ---------------------------------------------------------------------------
// helpers (base ISA only: ldmatrix + mma.sync)
// ---------------------------------------------------------------------------
__device__ __forceinline__ uint32_t smem_u32(const void* p) {
    uint32_t a;
    asm("{ .reg .u64 t; cvta.to.shared.u64 t, %1; cvt.u32.u64 %0, t; }"
        : "=r"(a) : "l"(p));
    return a;
}

__device__ __forceinline__ void ldmatrix_x4(uint32_t& r0, uint32_t& r1,
                                            uint32_t& r2, uint32_t& r3,
                                            uint32_t addr) {
    asm volatile("ldmatrix.sync.aligned.m8n8.x4.shared.b16 {%0,%1,%2,%3}, [%4];"
                 : "=r"(r0), "=r"(r1), "=r"(r2), "=r"(r3) : "r"(addr));
}

__device__ __forceinline__ void mma_f16(float* c, uint32_t a0, uint32_t a1,
                                        uint32_t a2, uint32_t a3,
                                        uint32_t b0, uint32_t b1) {
    asm volatile(
        "mma.sync.aligned.m16n8k16.row.col.f32.f16.f16.f32 "
        "{%0,%1,%2,%3}, {%4,%5,%6,%7}, {%8,%9}, {%0,%1,%2,%3};"
        : "+f"(c[0]), "+f"(c[1]), "+f"(c[2]), "+f"(c[3])
        : "r"(a0), "r"(a1), "r"(a2), "r"(a3), "r"(b0), "r"(b1));
}

// pack two fp32 into f16x2 word: low16 = x0, high16 = x1
__device__ __forceinline__ uint32_t cvt_f16x2(float x1, float x0) {
    uint32_t w;
    asm("cvt.rn.f16x2.f32 %0, %1, %2;" : "=r"(w) : "f"(x1), "f"(x0));
    return w;
}

// SMEM layout (bytes). V rows padded to 144B (64 f16 + 8 pad) => conflict-free.
#define ROWB 144
#define SM_V     0                /* 128 * 144 = 18432 */
#define SM_QS    18432            /* [128][64] f32 = 32768 */
#define SM_FUSED 51200            /* [64][128] f32 = 32768 */
#define SM_TOTAL 83968

// ---------------------------------------------------------------------------
// Kernel A: fused in-projection  out = X_s @ W_s^T + b_s  -> q/k/v [i][t][hd]
// 64-row x 64-col tiles, grid (24, 16)  [R4 version — best measured]
// ---------------------------------------------------------------------------
__global__ __launch_bounds__(256) void proj_in_kernel(
    const float* __restrict__ q_in, const float* __restrict__ k_in,
    const float* __restrict__ v_in, const float* __restrict__ W,
    const float* __restrict__ bias)
{
    const int jbase = blockIdx.x * 64;     // 0..1535
    const int rbase = blockIdx.y * 64;     // 0..1023
    const int section = jbase / 512;       // 0=q,1=k,2=v
    const float* __restrict__ X = (section == 0) ? q_in : (section == 1) ? k_in : v_in;

    __shared__ float Xs[16][64];
    __shared__ float Ws[16][64];

    const int tid = threadIdx.x;
    const int tx = tid & 15;
    const int ty = tid >> 4;

    float acc[4][4];
#pragma unroll
    for (int i = 0; i < 4; i++)
#pragma unroll
        for (int j = 0; j < 4; j++) acc[i][j] = 0.f;

    for (int k0 = 0; k0 < 512; k0 += 16) {
        {
            int r = tid >> 2;
            int kk = (tid & 3) * 4;
            float4 xv = *(const float4*)&X[(size_t)(rbase + r) * 512 + k0 + kk];
            Xs[kk + 0][r] = xv.x; Xs[kk + 1][r] = xv.y;
            Xs[kk + 2][r] = xv.z; Xs[kk + 3][r] = xv.w;
            float4 wv = *(const float4*)&W[(size_t)(jbase + r) * 512 + k0 + kk];
            Ws[kk + 0][r] = wv.x; Ws[kk + 1][r] = wv.y;
            Ws[kk + 2][r] = wv.z; Ws[kk + 3][r] = wv.w;
        }
        __syncthreads();
#pragma unroll
        for (int kk = 0; kk < 16; kk++) {
            float a0[4], b0[4];
            *(float4*)&a0[0] = *(float4*)&Xs[kk][ty * 4];
            *(float4*)&b0[0] = *(float4*)&Ws[kk][tx * 4];
#pragma unroll
            for (int i = 0; i < 4; i++)
#pragma unroll
                for (int j = 0; j < 4; j++) acc[i][j] += a0[i] * b0[j];
        }
        __syncthreads();
    }

    float* dst = (section == 0) ? g_q : (section == 1) ? g_k : g_v;
#pragma unroll
    for (int i = 0; i < 4; i++) {
        int r = rbase + ty * 4 + i;
        int t = r >> 3;
        int bb = r & 7;
#pragma unroll
        for (int j = 0; j < 4; j++) {
            int jg = jbase + tx * 4 + j;
            float val = acc[i][j] + bias[jg];
            int jj = jg & 511;
            int h = jj >> 6;
            int dp = jj & 63;
            if (section == 0) val *= SCALING;
            dst[(((size_t)(bb * 8 + h)) * 128 + t) * 64 + dp] = val;
        }
    }
}

// ---------------------------------------------------------------------------
// Kernel B v7: fp16 mma.sync trilinear, register-built A fragments, 16 warps.
// (v6 with the missing a0 offset in the q-row pointers FIXED)
// Block = (head, ahalf, batch) -> 64 'a' rows of pair i. Warp w:
//   b-window = (w&7)*16 rows, a-subrange = (w>>3)*32 .. +32.
// ---------------------------------------------------------------------------
__global__ __launch_bounds__(512, 1) void tri_main_v7(const float* __restrict__ cbias)
{
    const int head  = blockIdx.x;   // 0..7
    const int ahalf = blockIdx.y;   // 0..1
    const int batch = blockIdx.z;   // 0..7
    const int i = batch * 8 + head;
    const int a0 = ahalf * 64;

    extern __shared__ char smem[];
    const uint32_t sbase = smem_u32(smem);
    float* qs    = (float*)(smem + SM_QS);
    float* fused = (float*)(smem + SM_FUSED);

    const int tid  = threadIdx.x;
    const int wid  = tid >> 5;       // 0..15
    const int lane = tid & 31;
    const int bwin = (wid & 7) * 16; // b-row window
    const int asub = (wid >> 3) * 32;

    const float* __restrict__ qi = g_q + (size_t)i * 8192;
    const float* __restrict__ ki = g_k + (size_t)i * 8192;
    const float* __restrict__ vi = g_v + (size_t)i * 8192;

    // qs <- full q (scaled), needed by prep and final bmm
    for (int idx = tid; idx < 8192; idx += 512) qs[idx] = qi[idx];

    // V -> fp16 padded rows. thread: row=tid/4, 16-elem quarter
    {
        const int row = tid >> 2;
        const int tq = (tid & 3) * 16;
        char* vd = smem + SM_V + row * ROWB;
        const float* src = vi + row * 64 + tq;
#pragma unroll
        for (int j = 0; j < 16; j += 4) {
            uint32_t w0 = cvt_f16x2(src[j + 1], src[j]);
            uint32_t w1 = cvt_f16x2(src[j + 3], src[j + 2]);
            *(uint2*)(vd + (tq + j) * 2) = make_uint2(w0, w1);
        }
    }

    const int g = lane >> 2;       // fragment row group
    const int tig = lane & 3;      // fragment col pair

    // K values this lane needs for A fragments: rows bwin+g, bwin+g+8;
    // cols 16*ks + 2*tig + {0,1,8,9}
    float kr0[16], kr1[16];
    {
        const float* krow0 = ki + (size_t)(bwin + g) * 64;
        const float* krow1 = krow0 + 8 * 64;
#pragma unroll
        for (int ks = 0; ks < 4; ks++) {
            int c = ks * 16 + 2 * tig;
            kr0[ks * 4 + 0] = krow0[c];     kr0[ks * 4 + 1] = krow0[c + 1];
            kr0[ks * 4 + 2] = krow0[c + 8]; kr0[ks * 4 + 3] = krow0[c + 9];
            kr1[ks * 4 + 0] = krow1[c];     kr1[ks * 4 + 1] = krow1[c + 1];
            kr1[ks * 4 + 2] = krow1[c + 8]; kr1[ks * 4 + 3] = krow1[c + 9];
        }
    }
    __syncthreads();

    // V ldmatrix base: x4 tiles = 4 consecutive k-octets of 8 n-rows
    const uint32_t v_ld = sbase + SM_V + (lane & 7) * ROWB + ((lane >> 3) * 16);

    const int browA = bwin + g;
    const float* __restrict__ bias_b = cbias + ((size_t)batch << 21);

#pragma unroll 1
    for (int ap = 0; ap < 16; ap++) {
        const int aA = asub + 2 * ap, aB = aA + 1;

        // ---- build A fragments for both a's directly in registers ----
        uint32_t fa0[16], fa1[16];   // [ks*4 + r]
        {
            const float* qA = qs + (a0 + aA) * 64;   // FIX: include a0
            const float* qB = qA + 64;
#pragma unroll
            for (int ks = 0; ks < 4; ks++) {
                int c = ks * 16 + 2 * tig;
                float2 qa01 = *(const float2*)&qA[c];
                float2 qa89 = *(const float2*)&qA[c + 8];
                float2 qb01 = *(const float2*)&qB[c];
                float2 qb89 = *(const float2*)&qB[c + 8];
                fa0[ks * 4 + 0] = cvt_f16x2(kr0[ks * 4 + 1] * qa01.y, kr0[ks * 4 + 0] * qa01.x);
                fa0[ks * 4 + 1] = cvt_f16x2(kr1[ks * 4 + 1] * qa01.y, kr1[ks * 4 + 0] * qa01.x);
                fa0[ks * 4 + 2] = cvt_f16x2(kr0[ks * 4 + 3] * qa89.y, kr0[ks * 4 + 2] * qa89.x);
                fa0[ks * 4 + 3] = cvt_f16x2(kr1[ks * 4 + 3] * qa89.y, kr1[ks * 4 + 2] * qa89.x);
                fa1[ks * 4 + 0] = cvt_f16x2(kr0[ks * 4 + 1] * qb01.y, kr0[ks * 4 + 0] * qb01.x);
                fa1[ks * 4 + 1] = cvt_f16x2(kr1[ks * 4 + 1] * qb01.y, kr1[ks * 4 + 0] * qb01.x);
                fa1[ks * 4 + 2] = cvt_f16x2(kr0[ks * 4 + 3] * qb89.y, kr0[ks * 4 + 2] * qb89.x);
                fa1[ks * 4 + 3] = cvt_f16x2(kr1[ks * 4 + 3] * qb89.y, kr1[ks * 4 + 2] * qb89.x);
            }
        }

        const float* __restrict__ bpA =
            bias_b + ((size_t)(a0 + aA) << 14) + (size_t)browA * 128;
        const float* __restrict__ bpB = bpA + (1 << 14);
        float psA0 = 0.f, psA1 = 0.f, pmA0 = -1e30f, pmA1 = -1e30f;
        float psB0 = 0.f, psB1 = 0.f, pmB0 = -1e30f, pmB1 = -1e30f;

#pragma unroll 2
        for (int nc = 0; nc < 16; nc++) {
            uint32_t b[8];
            ldmatrix_x4(b[0], b[1], b[2], b[3], v_ld + nc * (8 * ROWB));
            ldmatrix_x4(b[4], b[5], b[6], b[7], v_ld + nc * (8 * ROWB) + 64);
            float c0[4] = {0.f, 0.f, 0.f, 0.f};
            float c1[4] = {0.f, 0.f, 0.f, 0.f};
#pragma unroll
            for (int ks = 0; ks < 4; ks++) {
                mma_f16(c0, fa0[ks * 4 + 0], fa0[ks * 4 + 1], fa0[ks * 4 + 2],
                        fa0[ks * 4 + 3], b[ks * 2], b[ks * 2 + 1]);
                mma_f16(c1, fa1[ks * 4 + 0], fa1[ks * 4 + 1], fa1[ks * 4 + 2],
                        fa1[ks * 4 + 3], b[ks * 2], b[ks * 2 + 1]);
            }
            const int col = nc * 8 + 2 * tig;
            float2 bA0 = *(const float2*)&bpA[col];
            float2 bA1 = *(const float2*)&bpA[8 * 128 + col];
            float2 bB0 = *(const float2*)&bpB[col];
            float2 bB1 = *(const float2*)&bpB[8 * 128 + col];
            {
                float s0 = c0[0] + bA0.x, s1 = c0[1] + bA0.y;
                float s2 = c0[2] + bA1.x, s3 = c0[3] + bA1.y;
                psA0 += s0 + s1; psA1 += s2 + s3;
                pmA0 = fmaxf(pmA0, fmaxf(s0, s1));
                pmA1 = fmaxf(pmA1, fmaxf(s2, s3));
            }
            {
                float s0 = c1[0] + bB0.x, s1 = c1[1] + bB0.y;
                float s2 = c1[2] + bB1.x, s3 = c1[3] + bB1.y;
                psB0 += s0 + s1; psB1 += s2 + s3;
                pmB0 = fmaxf(pmB0, fmaxf(s0, s1));
                pmB1 = fmaxf(pmB1, fmaxf(s2, s3));
            }
        }
        // quad reduce (cols spread over 4 tig lanes)
#pragma unroll
        for (int off = 1; off <= 2; off <<= 1) {
            psA0 += __shfl_xor_sync(0xffffffffu, psA0, off);
            psA1 += __shfl_xor_sync(0xffffffffu, psA1, off);
            psB0 += __shfl_xor_sync(0xffffffffu, psB0, off);
            psB1 += __shfl_xor_sync(0xffffffffu, psB1, off);
            pmA0 = fmaxf(pmA0, __shfl_xor_sync(0xffffffffu, pmA0, off));
            pmA1 = fmaxf(pmA1, __shfl_xor_sync(0xffffffffu, pmA1, off));
            pmB0 = fmaxf(pmB0, __shfl_xor_sync(0xffffffffu, pmB0, off));
            pmB1 = fmaxf(pmB1, __shfl_xor_sync(0xffffffffu, pmB1, off));
        }
        if (tig == 0) {
            fused[aA * 128 + browA]     = psA0 * (1.0f / 128.0f) + pmA0;
            fused[aA * 128 + browA + 8] = psA1 * (1.0f / 128.0f) + pmA1;
            fused[aB * 128 + browA]     = psB0 * (1.0f / 128.0f) + pmB0;
            fused[aB * 128 + browA + 8] = psB1 * (1.0f / 128.0f) + pmB1;
        }
    }
    __syncthreads();

    // Softmax over b for each of the 64 rows (one warp per row, round-robin)
    for (int a = wid; a < 64; a += 16) {
        float4 fv = *(float4*)&fused[a * 128 + lane * 4];
        float m = fmaxf(fmaxf(fv.x, fv.y), fmaxf(fv.z, fv.w));
#pragma unroll
        for (int off = 16; off >= 1; off >>= 1)
            m = fmaxf(m, __shfl_xor_sync(0xffffffffu, m, off));
        float e0 = __expf(fv.x - m), e1 = __expf(fv.y - m);
        float e2 = __expf(fv.z - m), e3 = __expf(fv.w - m);
        float s = (e0 + e1) + (e2 + e3);
#pragma unroll
        for (int off = 16; off >= 1; off >>= 1)
            s += __shfl_xor_sync(0xffffffffu, s, off);
        float inv = 1.0f / s;
        *(float4*)&fused[a * 128 + lane * 4] =
            make_float4(e0 * inv, e1 * inv, e2 * inv, e3 * inv);
    }
    __syncthreads();

    // attn[a, :] = sum_b w[a,b] q[b,:]; thread: a=tid/8 (64 rows), 8 cols
    {
        int a = tid >> 3;
        int dg = (tid & 7) * 8;
        float o[8];
#pragma unroll
        for (int j = 0; j < 8; j++) o[j] = 0.f;
        const float* wrow = fused + a * 128;
#pragma unroll 4
        for (int b = 0; b < 128; b++) {
            float wb = wrow[b];
            const float* qr = qs + b * 64 + dg;
            float4 q0 = *(const float4*)&qr[0];
            float4 q1 = *(const float4*)&qr[4];
            o[0] += wb * q0.x; o[1] += wb * q0.y;
            o[2] += wb * q0.z; o[3] += wb * q0.w;
            o[4] += wb * q1.x; o[5] += wb * q1.y;
            o[6] += wb * q1.z; o[7] += wb * q1.w;
        }
        int t = a0 + a;
        float* dst = g_attn2 + ((size_t)t * 8 + batch) * 512 + head * 64 + dg;
        *(float4*)&dst[0] = make_float4(o[0], o[1], o[2], o[3]);
        *(float4*)&dst[4] = make_float4(o[4], o[5], o[6], o[7]);
    }
}

// ---------------------------------------------------------------------------
// Kernel C: output projection (64-row x 64-col tiles, grid (8, 16))
// ---------------------------------------------------------------------------
__global__ __launch_bounds__(256) void proj_out_kernel(
    const float* __restrict__ W, const float* __restrict__ bias,
    float* __restrict__ out)
{
    const int jbase = blockIdx.x * 64;
    const int rbase = blockIdx.y * 64;
    const float* __restrict__ X = g_attn2;

    __shared__ float Xs[16][64];
    __shared__ float Ws[16][64];

    const int tid = threadIdx.x;
    const int tx = tid & 15;
    const int ty = tid >> 4;

    float acc[4][4];
#pragma unroll
    for (int i = 0; i < 4; i++)
#pragma unroll
        for (int j = 0; j < 4; j++) acc[i][j] = 0.f;

    for (int k0 = 0; k0 < 512; k0 += 16) {
        {
            int r = tid >> 2;
            int kk = (tid & 3) * 4;
            float4 xv = *(const float4*)&X[(size_t)(rbase + r) * 512 + k0 + kk];
            Xs[kk + 0][r] = xv.x; Xs[kk + 1][r] = xv.y;
            Xs[kk + 2][r] = xv.z; Xs[kk + 3][r] = xv.w;
            float4 wv = *(const float4*)&W[(size_t)(jbase + r) * 512 + k0 + kk];
            Ws[kk + 0][r] = wv.x; Ws[kk + 1][r] = wv.y;
            Ws[kk + 2][r] = wv.z; Ws[kk + 3][r] = wv.w;
        }
        __syncthreads();
#pragma unroll
        for (int kk = 0; kk < 16; kk++) {
            float a0[4], b0[4];
            *(float4*)&a0[0] = *(float4*)&Xs[kk][ty * 4];
            *(float4*)&b0[0] = *(float4*)&Ws[kk][tx * 4];
#pragma unroll
            for (int i = 0; i < 4; i++)
#pragma unroll
                for (int j = 0; j < 4; j++) acc[i][j] += a0[i] * b0[j];
        }
        __syncthreads();
    }

#pragma unroll
    for (int i = 0; i < 4; i++) {
        int r = rbase + ty * 4 + i;
#pragma unroll
        for (int j = 0; j < 4; j++) {
            int jg = jbase + tx * 4 + j;
            out[(size_t)r * 512 + jg] = acc[i][j] + bias[jg];
        }
    }
}

// ---------------------------------------------------------------------------
extern "C" void kernel_launch(void* const* d_in, const int* in_sizes, int n_in,
                              void* d_out, int out_size)
{
    const float* query = (const float*)d_in[0];
    const float* key   = (const float*)d_in[1];
    const float* value = (const float*)d_in[2];
    const float* cbias = (const float*)d_in[3];
    const float* ipw   = (const float*)d_in[4];
    const float* ipb   = (const float*)d_in[5];
    const float* outw  = (const float*)d_in[6];
    const float* outb  = (const float*)d_in[7];
    float* out = (float*)d_out;

    proj_in_kernel<<<dim3(24, 16), 256>>>(query, key, value, ipw, ipb);

    cudaFuncSetAttribute(tri_main_v7,
                         cudaFuncAttributeMaxDynamicSharedMemorySize, SM_TOTAL);
    tri_main_v7<<<dim3(8, 2, 8), 512, SM_TOTAL>>>(cbias);

    proj_out_kernel<<<dim3(8, 16), 256>>>(outw, outb, out);
}

// round 9
// speedup vs baseline: 3.1277x; 1.1508x over previous
#include <cuda_runtime.h>
#include <cuda_fp16.h>
#include <cuda_bf16.h>
#include <math.h>
#include <stdint.h>

#define EMBED_DIM 512
#define NUM_HEADS 8
#define HEAD_DIM 64
#define T_LEN 128
#define BATCH 8
#define BH 64
#define SCALING 0.125f
#define LAMBDA 1.0f

// Scratch (allocation-free rule: __device__ globals)
__device__ float g_q[BH * T_LEN * HEAD_DIM];     // [i][t][hd], scaled
__device__ float g_k[BH * T_LEN * HEAD_DIM];
__device__ float g_v[BH * T_LEN * HEAD_DIM];
__device__ float g_attn2[T_LEN * BATCH * EMBED_DIM];  // [t][b][h*64+d]

// ---------------------------------------------------------------------------
// helpers (base ISA only: ldmatrix + mma.sync)
// ---------------------------------------------------------------------------
__device__ __forceinline__ uint32_t smem_u32(const void* p) {
    uint32_t a;
    asm("{ .reg .u64 t; cvta.to.shared.u64 t, %1; cvt.u32.u64 %0, t; }"
        : "=r"(a) : "l"(p));
    return a;
}

__device__ __forceinline__ void ldmatrix_x4(uint32_t& r0, uint32_t& r1,
                                            uint32_t& r2, uint32_t& r3,
                                            uint32_t addr) {
    asm volatile("ldmatrix.sync.aligned.m8n8.x4.shared.b16 {%0,%1,%2,%3}, [%4];"
                 : "=r"(r0), "=r"(r1), "=r"(r2), "=r"(r3) : "r"(addr));
}

__device__ __forceinline__ void mma_f16(float* c, uint32_t a0, uint32_t a1,
                                        uint32_t a2, uint32_t a3,
                                        uint32_t b0, uint32_t b1) {
    asm volatile(
        "mma.sync.aligned.m16n8k16.row.col.f32.f16.f16.f32 "
        "{%0,%1,%2,%3}, {%4,%5,%6,%7}, {%8,%9}, {%0,%1,%2,%3};"
        : "+f"(c[0]), "+f"(c[1]), "+f"(c[2]), "+f"(c[3])
        : "r"(a0), "r"(a1), "r"(a2), "r"(a3), "r"(b0), "r"(b1));
}

// pack two fp32 into f16x2 word: low16 = x0, high16 = x1
__device__ __forceinline__ uint32_t cvt_f16x2(float x1, float x0) {
    uint32_t w;
    asm("cvt.rn.f16x2.f32 %0, %1, %2;" : "=r"(w) : "f"(x1), "f"(x0));
    return w;
}

// hi/lo split of 4 floats into packed f16 words (hi = rn(x), lo = rn(x - hi))
__device__ __forceinline__ void split4(float4 v, uint32_t& h0, uint32_t& h1,
                                       uint32_t& l0, uint32_t& l1) {
    h0 = cvt_f16x2(v.y, v.x);
    h1 = cvt_f16x2(v.w, v.z);
    float hx = __half2float(__ushort_as_half((unsigned short)(h0 & 0xFFFF)));
    float hy = __half2float(__ushort_as_half((unsigned short)(h0 >> 16)));
    float hz = __half2float(__ushort_as_half((unsigned short)(h1 & 0xFFFF)));
    float hw = __half2float(__ushort_as_half((unsigned short)(h1 >> 16)));
    l0 = cvt_f16x2(v.y - hy, v.x - hx);
    l1 = cvt_f16x2(v.w - hw, v.z - hz);
}

// SMEM layout (bytes). Rows padded to 144B (64 f16 + 8 pad) => conflict-free.
#define ROWB 144
#define SM_V     0                /* 128 * 144 = 18432 */
#define SM_QS    18432            /* [128][64] f32 = 32768 */
#define SM_FUSED 51200            /* [64][128] f32 = 32768 */
#define SM_TOTAL 83968

// ---------------------------------------------------------------------------
// Projection GEMM on tensor cores with 3-term fp16 hi/lo split (fp32-accurate)
// C[64rows x 64cols] tile per 128-thread block; K=512 in chunks of 64.
// mode 0: in-projection (X from q/k/v by column section; scatter to g_q/k/v)
// mode 1: out-projection (X = g_attn2; direct store to outp)
// ---------------------------------------------------------------------------
#define PJ_XH 0
#define PJ_XL 9216
#define PJ_WH 18432
#define PJ_WL 27648

__global__ __launch_bounds__(128) void gemm_proj_kernel(
    const float* __restrict__ xq, const float* __restrict__ xk,
    const float* __restrict__ xv, const float* __restrict__ W,
    const float* __restrict__ bias, float* __restrict__ outp, int mode)
{
    const int jbase = blockIdx.x * 64;
    const int rbase = blockIdx.y * 64;

    int section = 0;
    const float* __restrict__ X;
    if (mode == 0) {
        section = jbase >> 9;
        X = (section == 0) ? xq : (section == 1) ? xk : xv;
    } else {
        X = g_attn2;
    }

    __shared__ char smem[36864];
    const uint32_t sbase = smem_u32(smem);

    const int tid = threadIdx.x;
    const int wid = tid >> 5;
    const int lane = tid & 31;

    // load-phase: thread owns row=tid/2 (0..63), half th
    const int row = tid >> 1;
    const int th = (tid & 1) * 32;
    const float* __restrict__ xsrc = X + (size_t)(rbase + row) * 512 + th;
    const float* __restrict__ wsrc = W + (size_t)(jbase + row) * 512 + th;
    char* xh = smem + PJ_XH + row * ROWB + th * 2;
    char* xl = smem + PJ_XL + row * ROWB + th * 2;
    char* wh = smem + PJ_WH + row * ROWB + th * 2;
    char* wl = smem + PJ_WL + row * ROWB + th * 2;

    // ldmatrix addresses (validated patterns from tri_main v3/v4)
    const uint32_t a_ldh = sbase + PJ_XH + (wid * 16 + (lane & 15)) * ROWB +
                           ((lane >= 16) ? 16 : 0);
    const uint32_t a_ldl = a_ldh + (PJ_XL - PJ_XH);
    const uint32_t b_ldh = sbase + PJ_WH + (lane & 7) * ROWB + ((lane >> 3) * 16);
    const uint32_t b_ldl = b_ldh + (PJ_WL - PJ_WH);

    float acc[8][4];
#pragma unroll
    for (int n = 0; n < 8; n++)
#pragma unroll
        for (int j = 0; j < 4; j++) acc[n][j] = 0.f;

#pragma unroll 1
    for (int kc = 0; kc < 8; kc++) {
        const int k0 = kc * 64;
        // load & hi/lo split into smem
#pragma unroll
        for (int j = 0; j < 32; j += 4) {
            float4 v4 = *(const float4*)&xsrc[k0 + j];
            uint32_t h0, h1, l0, l1;
            split4(v4, h0, h1, l0, l1);
            *(uint2*)(xh + j * 2) = make_uint2(h0, h1);
            *(uint2*)(xl + j * 2) = make_uint2(l0, l1);
            float4 w4 = *(const float4*)&wsrc[k0 + j];
            split4(w4, h0, h1, l0, l1);
            *(uint2*)(wh + j * 2) = make_uint2(h0, h1);
            *(uint2*)(wl + j * 2) = make_uint2(l0, l1);
        }
        __syncthreads();

        // A fragments for this warp's 16 rows, all 4 k-steps, hi+lo
        uint32_t ah[16], al[16];
#pragma unroll
        for (int ks = 0; ks < 4; ks++) {
            ldmatrix_x4(ah[ks * 4 + 0], ah[ks * 4 + 1], ah[ks * 4 + 2],
                        ah[ks * 4 + 3], a_ldh + ks * 32);
            ldmatrix_x4(al[ks * 4 + 0], al[ks * 4 + 1], al[ks * 4 + 2],
                        al[ks * 4 + 3], a_ldl + ks * 32);
        }

#pragma unroll
        for (int nc = 0; nc < 8; nc++) {
            uint32_t bh[8], bl[8];
            ldmatrix_x4(bh[0], bh[1], bh[2], bh[3], b_ldh + nc * (8 * ROWB));
            ldmatrix_x4(bh[4], bh[5], bh[6], bh[7], b_ldh + nc * (8 * ROWB) + 64);
            ldmatrix_x4(bl[0], bl[1], bl[2], bl[3], b_ldl + nc * (8 * ROWB));
            ldmatrix_x4(bl[4], bl[5], bl[6], bl[7], b_ldl + nc * (8 * ROWB) + 64);
#pragma unroll
            for (int ks = 0; ks < 4; ks++) {
                mma_f16(acc[nc], ah[ks * 4 + 0], ah[ks * 4 + 1], ah[ks * 4 + 2],
                        ah[ks * 4 + 3], bh[ks * 2], bh[ks * 2 + 1]);
                mma_f16(acc[nc], ah[ks * 4 + 0], ah[ks * 4 + 1], ah[ks * 4 + 2],
                        ah[ks * 4 + 3], bl[ks * 2], bl[ks * 2 + 1]);
                mma_f16(acc[nc], al[ks * 4 + 0], al[ks * 4 + 1], al[ks * 4 + 2],
                        al[ks * 4 + 3], bh[ks * 2], bh[ks * 2 + 1]);
            }
        }
        __syncthreads();
    }

    // epilogue: fragment (row r0/r0+8, col jg/jg+1) per acc[nc]
    const int g = lane >> 2;
    const int tig = lane & 3;
    const int r0 = rbase + wid * 16 + g;

#pragma unroll
    for (int nc = 0; nc < 8; nc++) {
        const int jg = jbase + nc * 8 + 2 * tig;
        const float b0 = bias[jg], b1 = bias[jg + 1];
        float v00 = acc[nc][0] + b0, v01 = acc[nc][1] + b1;
        float v10 = acc[nc][2] + b0, v11 = acc[nc][3] + b1;
        if (mode == 0) {
            if (section == 0) { v00 *= SCALING; v01 *= SCALING;
                                v10 *= SCALING; v11 *= SCALING; }
            float* dst = (section == 0) ? g_q : (section == 1) ? g_k : g_v;
            const int jj = jg & 511;
            const int h = jj >> 6;
            const int dp = jj & 63;
#pragma unroll
            for (int rr = 0; rr < 2; rr++) {
                const int r = r0 + rr * 8;
                const int t = r >> 3;
                const int bb = r & 7;
                float2 val = rr ? make_float2(v10, v11) : make_float2(v00, v01);
                *(float2*)&dst[(((size_t)(bb * 8 + h)) * 128 + t) * 64 + dp] = val;
            }
        } else {
            *(float2*)&outp[(size_t)r0 * 512 + jg] = make_float2(v00, v01);
            *(float2*)&outp[(size_t)(r0 + 8) * 512 + jg] = make_float2(v10, v11);
        }
    }
}

// ---------------------------------------------------------------------------
// Kernel B v7: fp16 mma.sync trilinear, register-built A fragments, 16 warps.
// (unchanged from R8 — passed at 221.7us total)
// ---------------------------------------------------------------------------
__global__ __launch_bounds__(512, 1) void tri_main_v7(const float* __restrict__ cbias)
{
    const int head  = blockIdx.x;   // 0..7
    const int ahalf = blockIdx.y;   // 0..1
    const int batch = blockIdx.z;   // 0..7
    const int i = batch * 8 + head;
    const int a0 = ahalf * 64;

    extern __shared__ char smem[];
    const uint32_t sbase = smem_u32(smem);
    float* qs    = (float*)(smem + SM_QS);
    float* fused = (float*)(smem + SM_FUSED);

    const int tid  = threadIdx.x;
    const int wid  = tid >> 5;       // 0..15
    const int lane = tid & 31;
    const int bwin = (wid & 7) * 16; // b-row window
    const int asub = (wid >> 3) * 32;

    const float* __restrict__ qi = g_q + (size_t)i * 8192;
    const float* __restrict__ ki = g_k + (size_t)i * 8192;
    const float* __restrict__ vi = g_v + (size_t)i * 8192;

    // qs <- full q (scaled), needed by prep and final bmm
    for (int idx = tid; idx < 8192; idx += 512) qs[idx] = qi[idx];

    // V -> fp16 padded rows. thread: row=tid/4, 16-elem quarter
    {
        const int row = tid >> 2;
        const int tq = (tid & 3) * 16;
        char* vd = smem + SM_V + row * ROWB;
        const float* src = vi + row * 64 + tq;
#pragma unroll
        for (int j = 0; j < 16; j += 4) {
            uint32_t w0 = cvt_f16x2(src[j + 1], src[j]);
            uint32_t w1 = cvt_f16x2(src[j + 3], src[j + 2]);
            *(uint2*)(vd + (tq + j) * 2) = make_uint2(w0, w1);
        }
    }

    const int g = lane >> 2;       // fragment row group
    const int tig = lane & 3;      // fragment col pair

    // K values this lane needs for A fragments: rows bwin+g, bwin+g+8;
    // cols 16*ks + 2*tig + {0,1,8,9}
    float kr0[16], kr1[16];
    {
        const float* krow0 = ki + (size_t)(bwin + g) * 64;
        const float* krow1 = krow0 + 8 * 64;
#pragma unroll
        for (int ks = 0; ks < 4; ks++) {
            int c = ks * 16 + 2 * tig;
            kr0[ks * 4 + 0] = krow0[c];     kr0[ks * 4 + 1] = krow0[c + 1];
            kr0[ks * 4 + 2] = krow0[c + 8]; kr0[ks * 4 + 3] = krow0[c + 9];
            kr1[ks * 4 + 0] = krow1[c];     kr1[ks * 4 + 1] = krow1[c + 1];
            kr1[ks * 4 + 2] = krow1[c + 8]; kr1[ks * 4 + 3] = krow1[c + 9];
        }
    }
    __syncthreads();

    // V ldmatrix base: x4 tiles = 4 consecutive k-octets of 8 n-rows
    const uint32_t v_ld = sbase + SM_V + (lane & 7) * ROWB + ((lane >> 3) * 16);

    const int browA = bwin + g;
    const float* __restrict__ bias_b = cbias + ((size_t)batch << 21);

#pragma unroll 1
    for (int ap = 0; ap < 16; ap++) {
        const int aA = asub + 2 * ap, aB = aA + 1;

        // ---- build A fragments for both a's directly in registers ----
        uint32_t fa0[16], fa1[16];   // [ks*4 + r]
        {
            const float* qA = qs + (a0 + aA) * 64;
            const float* qB = qA + 64;
#pragma unroll
            for (int ks = 0; ks < 4; ks++) {
                int c = ks * 16 + 2 * tig;
                float2 qa01 = *(const float2*)&qA[c];
                float2 qa89 = *(const float2*)&qA[c + 8];
                float2 qb01 = *(const float2*)&qB[c];
                float2 qb89 = *(const float2*)&qB[c + 8];
                fa0[ks * 4 + 0] = cvt_f16x2(kr0[ks * 4 + 1] * qa01.y, kr0[ks * 4 + 0] * qa01.x);
                fa0[ks * 4 + 1] = cvt_f16x2(kr1[ks * 4 + 1] * qa01.y, kr1[ks * 4 + 0] * qa01.x);
                fa0[ks * 4 + 2] = cvt_f16x2(kr0[ks * 4 + 3] * qa89.y, kr0[ks * 4 + 2] * qa89.x);
                fa0[ks * 4 + 3] = cvt_f16x2(kr1[ks * 4 + 3] * qa89.y, kr1[ks * 4 + 2] * qa89.x);
                fa1[ks * 4 + 0] = cvt_f16x2(kr0[ks * 4 + 1] * qb01.y, kr0[ks * 4 + 0] * qb01.x);
                fa1[ks * 4 + 1] = cvt_f16x2(kr1[ks * 4 + 1] * qb01.y, kr1[ks * 4 + 0] * qb01.x);
                fa1[ks * 4 + 2] = cvt_f16x2(kr0[ks * 4 + 3] * qb89.y, kr0[ks * 4 + 2] * qb89.x);
                fa1[ks * 4 + 3] = cvt_f16x2(kr1[ks * 4 + 3] * qb89.y, kr1[ks * 4 + 2] * qb89.x);
            }
        }

        const float* __restrict__ bpA =
            bias_b + ((size_t)(a0 + aA) << 14) + (size_t)browA * 128;
        const float* __restrict__ bpB = bpA + (1 << 14);
        float psA0 = 0.f, psA1 = 0.f, pmA0 = -1e30f, pmA1 = -1e30f;
        float psB0 = 0.f, psB1 = 0.f, pmB0 = -1e30f, pmB1 = -1e30f;

#pragma unroll 2
        for (int nc = 0; nc < 16; nc++) {
            uint32_t b[8];
            ldmatrix_x4(b[0], b[1], b[2], b[3], v_ld + nc * (8 * ROWB));
            ldmatrix_x4(b[4], b[5], b[6], b[7], v_ld + nc * (8 * ROWB) + 64);
            float c0[4] = {0.f, 0.f, 0.f, 0.f};
            float c1[4] = {0.f, 0.f, 0.f, 0.f};
#pragma unroll
            for (int ks = 0; ks < 4; ks++) {
                mma_f16(c0, fa0[ks * 4 + 0], fa0[ks * 4 + 1], fa0[ks * 4 + 2],
                        fa0[ks * 4 + 3], b[ks * 2], b[ks * 2 + 1]);
                mma_f16(c1, fa1[ks * 4 + 0], fa1[ks * 4 + 1], fa1[ks * 4 + 2],
                        fa1[ks * 4 + 3], b[ks * 2], b[ks * 2 + 1]);
            }
            const int col = nc * 8 + 2 * tig;
            float2 bA0 = *(const float2*)&bpA[col];
            float2 bA1 = *(const float2*)&bpA[8 * 128 + col];
            float2 bB0 = *(const float2*)&bpB[col];
            float2 bB1 = *(const float2*)&bpB[8 * 128 + col];
            {
                float s0 = c0[0] + bA0.x, s1 = c0[1] + bA0.y;
                float s2 = c0[2] + bA1.x, s3 = c0[3] + bA1.y;
                psA0 += s0 + s1; psA1 += s2 + s3;
                pmA0 = fmaxf(pmA0, fmaxf(s0, s1));
                pmA1 = fmaxf(pmA1, fmaxf(s2, s3));
            }
            {
                float s0 = c1[0] + bB0.x, s1 = c1[1] + bB0.y;
                float s2 = c1[2] + bB1.x, s3 = c1[3] + bB1.y;
                psB0 += s0 + s1; psB1 += s2 + s3;
                pmB0 = fmaxf(pmB0, fmaxf(s0, s1));
                pmB1 = fmaxf(pmB1, fmaxf(s2, s3));
            }
        }
        // quad reduce (cols spread over 4 tig lanes)
#pragma unroll
        for (int off = 1; off <= 2; off <<= 1) {
            psA0 += __shfl_xor_sync(0xffffffffu, psA0, off);
            psA1 += __shfl_xor_sync(0xffffffffu, psA1, off);
            psB0 += __shfl_xor_sync(0xffffffffu, psB0, off);
            psB1 += __shfl_xor_sync(0xffffffffu, psB1, off);
            pmA0 = fmaxf(pmA0, __shfl_xor_sync(0xffffffffu, pmA0, off));
            pmA1 = fmaxf(pmA1, __shfl_xor_sync(0xffffffffu, pmA1, off));
            pmB0 = fmaxf(pmB0, __shfl_xor_sync(0xffffffffu, pmB0, off));
            pmB1 = fmaxf(pmB1, __shfl_xor_sync(0xffffffffu, pmB1, off));
        }
        if (tig == 0) {
            fused[aA * 128 + browA]     = psA0 * (1.0f / 128.0f) + pmA0;
            fused[aA * 128 + browA + 8] = psA1 * (1.0f / 128.0f) + pmA1;
            fused[aB * 128 + browA]     = psB0 * (1.0f / 128.0f) + pmB0;
            fused[aB * 128 + browA + 8] = psB1 * (1.0f / 128.0f) + pmB1;
        }
    }
    __syncthreads();

    // Softmax over b for each of the 64 rows (one warp per row, round-robin)
    for (int a = wid; a < 64; a += 16) {
        float4 fv = *(float4*)&fused[a * 128 + lane * 4];
        float m = fmaxf(fmaxf(fv.x, fv.y), fmaxf(fv.z, fv.w));
#pragma unroll
        for (int off = 16; off >= 1; off >>= 1)
            m = fmaxf(m, __shfl_xor_sync(0xffffffffu, m, off));
        float e0 = __expf(fv.x - m), e1 = __expf(fv.y - m);
        float e2 = __expf(fv.z - m), e3 = __expf(fv.w - m);
        float s = (e0 + e1) + (e2 + e3);
#pragma unroll
        for (int off = 16; off >= 1; off >>= 1)
            s += __shfl_xor_sync(0xffffffffu, s, off);
        float inv = 1.0f / s;
        *(float4*)&fused[a * 128 + lane * 4] =
            make_float4(e0 * inv, e1 * inv, e2 * inv, e3 * inv);
    }
    __syncthreads();

    // attn[a, :] = sum_b w[a,b] q[b,:]; thread: a=tid/8 (64 rows), 8 cols
    {
        int a = tid >> 3;
        int dg = (tid & 7) * 8;
        float o[8];
#pragma unroll
        for (int j = 0; j < 8; j++) o[j] = 0.f;
        const float* wrow = fused + a * 128;
#pragma unroll 4
        for (int b = 0; b < 128; b++) {
            float wb = wrow[b];
            const float* qr = qs + b * 64 + dg;
            float4 q0 = *(const float4*)&qr[0];
            float4 q1 = *(const float4*)&qr[4];
            o[0] += wb * q0.x; o[1] += wb * q0.y;
            o[2] += wb * q0.z; o[3] += wb * q0.w;
            o[4] += wb * q1.x; o[5] += wb * q1.y;
            o[6] += wb * q1.z; o[7] += wb * q1.w;
        }
        int t = a0 + a;
        float* dst = g_attn2 + ((size_t)t * 8 + batch) * 512 + head * 64 + dg;
        *(float4*)&dst[0] = make_float4(o[0], o[1], o[2], o[3]);
        *(float4*)&dst[4] = make_float4(o[4], o[5], o[6], o[7]);
    }
}

// ---------------------------------------------------------------------------
extern "C" void kernel_launch(void* const* d_in, const int* in_sizes, int n_in,
                              void* d_out, int out_size)
{
    const float* query = (const float*)d_in[0];
    const float* key   = (const float*)d_in[1];
    const float* value = (const float*)d_in[2];
    const float* cbias = (const float*)d_in[3];
    const float* ipw   = (const float*)d_in[4];
    const float* ipb   = (const float*)d_in[5];
    const float* outw  = (const float*)d_in[6];
    const float* outb  = (const float*)d_in[7];
    float* out = (float*)d_out;

    // in-projection on tensor cores (3-term fp16 split, fp32-accurate)
    gemm_proj_kernel<<<dim3(24, 16), 128>>>(query, key, value, ipw, ipb,
                                            nullptr, 0);

    cudaFuncSetAttribute(tri_main_v7,
                         cudaFuncAttributeMaxDynamicSharedMemorySize, SM_TOTAL);
    tri_main_v7<<<dim3(8, 2, 8), 512, SM_TOTAL>>>(cbias);

    // out-projection (X = g_attn2 selected inside kernel via mode=1)
    gemm_proj_kernel<<<dim3(8, 16), 128>>>(nullptr, nullptr, nullptr, outw,
                                           outb, out, 1);
}